// round 16
// baseline (speedup 1.0000x reference)
#include <cuda_runtime.h>
#include <cuda_fp16.h>
#include <math.h>
#include <stdint.h>

#define BATCH 4
#define NN 4096
#define CC 128
#define QT 128
#define MT 128
#define ITERS (NN / MT)

// f16 scratch, row-major [b*n][c]. Fb is pre-scaled by log2(e).
__device__ __align__(16) __half Fb[BATCH * NN * CC];
__device__ __align__(16) __half Gb[BATCH * NN * CC];
__device__ __align__(16) __half Vb[BATCH * NN * CC];

// ===================== helpers =====================
__device__ __forceinline__ uint32_t smem_u32(const void* p) {
    uint32_t a;
    asm("{ .reg .u64 t; cvta.to.shared.u64 t, %1; cvt.u32.u64 %0, t; }" : "=r"(a) : "l"(p));
    return a;
}
__device__ __forceinline__ uint32_t pack_f16x2(float lo, float hi) {
    uint32_t r;
    asm("cvt.rn.f16x2.f32 %0, %1, %2;" : "=r"(r) : "f"(hi), "f"(lo));
    return r;
}
__device__ __forceinline__ uint32_t ex2_f16x2(uint32_t a) {
    uint32_t r;
    asm("ex2.approx.f16x2 %0, %1;" : "=r"(r) : "r"(a));
    return r;
}
__device__ __forceinline__ uint32_t hadd2u(uint32_t a, uint32_t b) {
    uint32_t r;
    asm("add.f16x2 %0, %1, %2;" : "=r"(r) : "r"(a), "r"(b));
    return r;
}
// blocked SW128 layout for a [128 rows][128 halves] f16 tile (32 KB)
__device__ __forceinline__ uint32_t blk_off(int r, int k) {
    uint32_t byte = ((uint32_t)((r >> 3) + ((k >> 6) << 4)) << 10)
                  + ((uint32_t)(r & 7) << 7) + ((uint32_t)(k & 63) << 1);
    return byte ^ ((byte >> 3) & 0x70);
}
__device__ __forceinline__ void ldsm_x4(uint32_t (&r)[4], uint32_t addr) {
    asm volatile("ldmatrix.sync.aligned.m8n8.x4.shared.b16 {%0,%1,%2,%3}, [%4];"
                 : "=r"(r[0]), "=r"(r[1]), "=r"(r[2]), "=r"(r[3]) : "r"(addr));
}
__device__ __forceinline__ void ldsm_x4_t(uint32_t (&r)[4], uint32_t addr) {
    asm volatile("ldmatrix.sync.aligned.m8n8.x4.trans.shared.b16 {%0,%1,%2,%3}, [%4];"
                 : "=r"(r[0]), "=r"(r[1]), "=r"(r[2]), "=r"(r[3]) : "r"(addr));
}
__device__ __forceinline__ void mma_f32acc(float (&d)[4], uint32_t a0, uint32_t a1,
                                           uint32_t a2, uint32_t a3,
                                           uint32_t b0, uint32_t b1) {
    asm volatile("mma.sync.aligned.m16n8k16.row.col.f32.f16.f16.f32 "
                 "{%0,%1,%2,%3},{%4,%5,%6,%7},{%8,%9},{%0,%1,%2,%3};"
                 : "+f"(d[0]), "+f"(d[1]), "+f"(d[2]), "+f"(d[3])
                 : "r"(a0), "r"(a1), "r"(a2), "r"(a3), "r"(b0), "r"(b1));
}
__device__ __forceinline__ void mma_f16acc2(uint32_t& d0, uint32_t& d1,
                                            uint32_t a0, uint32_t a1,
                                            uint32_t a2, uint32_t a3,
                                            uint32_t b0, uint32_t b1) {
    asm volatile("mma.sync.aligned.m16n8k16.row.col.f16.f16.f16.f16 "
                 "{%0,%1},{%2,%3,%4,%5},{%6,%7},{%0,%1};"
                 : "+r"(d0), "+r"(d1)
                 : "r"(a0), "r"(a1), "r"(a2), "r"(a3), "r"(b0), "r"(b1));
}
__device__ __forceinline__ void cp16(uint32_t d, const void* s) {
    asm volatile("cp.async.cg.shared.global [%0], [%1], 16;" :: "r"(d), "l"(s) : "memory");
}
#define CP_COMMIT() asm volatile("cp.async.commit_group;" ::: "memory")
#define CP_WAITALL() asm volatile("cp.async.wait_group 0;" ::: "memory")

#define MBAR_INIT(a, c) \
    asm volatile("mbarrier.init.shared.b64 [%0], %1;" :: "r"(a), "r"((uint32_t)(c)) : "memory")
#define MBAR_ARRIVE(a) \
    asm volatile("mbarrier.arrive.shared.b64 _, [%0];" :: "r"(a) : "memory")
#define MBAR_WAIT(a, par) do { \
    uint32_t _a = (a), _p = (uint32_t)(par), _d; \
    asm volatile("{ .reg .pred p; mbarrier.try_wait.parity.acquire.cta.shared::cta.b64 p, [%1], %2; selp.b32 %0,1,0,p; }" \
                 : "=r"(_d) : "r"(_a), "r"(_p) : "memory"); \
    if (!_d) { \
        asm volatile("{ .reg .pred P1; WL_%=: mbarrier.try_wait.parity.acquire.cta.shared::cta.b64 P1, [%0], %1, 0x989680; @P1 bra.uni WD_%=; bra.uni WL_%=; WD_%=: }" \
                     :: "r"(_a), "r"(_p) : "memory"); \
    } \
} while (0)

#define LOG2E 1.4426950408889634f

// ===================== Kernel A: projections, one weight per CTA =====================
__global__ __launch_bounds__(256, 1)
void proj_kernel(const float* __restrict__ x,
                 const float* __restrict__ Wf, const float* __restrict__ bf,
                 const float* __restrict__ Wg, const float* __restrict__ bg,
                 const float* __restrict__ Wh, const float* __restrict__ bh)
{
    extern __shared__ char smraw[];
    const uint32_t sbase = smem_u32(smraw);
    const uint32_t sal   = (sbase + 1023u) & ~1023u;
    char* smp = smraw + (sal - sbase);
    const uint32_t XT = sal, WT = sal + 32768;

    const int tid  = threadIdx.x;
    const int lane = tid & 31;
    const int wid  = tid >> 5;
    const int wm   = wid & 3;
    const int wn   = wid >> 2;
    const int row0 = blockIdx.x * 128;
    const int w    = blockIdx.y;

    const float* W  = (w == 0) ? Wf : (w == 1 ? Wg : Wh);
    const float* bs = (w == 0) ? bf : (w == 1 ? bg : bh);

    #pragma unroll
    for (int idx = tid; idx < 2048; idx += 256) {
        int r = idx >> 4, kc = idx & 15;
        const float4* s0 = (const float4*)(x + (size_t)(row0 + r) * CC + kc * 8);
        const float4* s1 = (const float4*)(W + (size_t)r * CC + kc * 8);
        float4 v0 = s0[0], v1 = s0[1];
        uint4 pk;
        pk.x = pack_f16x2(v0.x, v0.y); pk.y = pack_f16x2(v0.z, v0.w);
        pk.z = pack_f16x2(v1.x, v1.y); pk.w = pack_f16x2(v1.z, v1.w);
        *(uint4*)(smp + (XT - sal) + blk_off(r, kc * 8)) = pk;
        v0 = s1[0]; v1 = s1[1];
        pk.x = pack_f16x2(v0.x, v0.y); pk.y = pack_f16x2(v0.z, v0.w);
        pk.z = pack_f16x2(v1.x, v1.y); pk.w = pack_f16x2(v1.z, v1.w);
        *(uint4*)(smp + (WT - sal) + blk_off(r, kc * 8)) = pk;
    }
    float bc[16];
    #pragma unroll
    for (int t = 0; t < 16; ++t)
        bc[t] = bs[64 * wn + 8 * (t >> 1) + 2 * (lane & 3) + (t & 1)];
    __syncthreads();

    float acc[2][8][4];
    #pragma unroll
    for (int i = 0; i < 2; ++i)
        #pragma unroll
        for (int j = 0; j < 8; ++j)
            #pragma unroll
            for (int e = 0; e < 4; ++e) acc[i][j][e] = 0.f;

    #pragma unroll
    for (int ks = 0; ks < 8; ++ks) {
        uint32_t a0[4], a1[4];
        int kcol = 16 * ks + 8 * (lane >> 4);
        ldsm_x4(a0, XT + blk_off(32 * wm + (lane & 15), kcol));
        ldsm_x4(a1, XT + blk_off(32 * wm + 16 + (lane & 15), kcol));
        #pragma unroll
        for (int g = 0; g < 4; ++g) {
            uint32_t bt[4];
            ldsm_x4_t(bt, WT + blk_off(16 * ks + (lane & 15),
                                       64 * wn + 16 * g + 8 * (lane >> 4)));
            mma_f32acc(acc[0][2 * g],     a0[0], a0[1], a0[2], a0[3], bt[0], bt[1]);
            mma_f32acc(acc[0][2 * g + 1], a0[0], a0[1], a0[2], a0[3], bt[2], bt[3]);
            mma_f32acc(acc[1][2 * g],     a1[0], a1[1], a1[2], a1[3], bt[0], bt[1]);
            mma_f32acc(acc[1][2 * g + 1], a1[0], a1[1], a1[2], a1[3], bt[2], bt[3]);
        }
    }

    const float osc = (w == 0) ? LOG2E : 1.0f;
    uint32_t* dst = (uint32_t*)(w == 0 ? Fb : (w == 1 ? Gb : Vb));
    #pragma unroll
    for (int mi = 0; mi < 2; ++mi)
        #pragma unroll
        for (int nj = 0; nj < 8; ++nj) {
            int row  = row0 + 32 * wm + 16 * mi + (lane >> 2);
            int colp = 32 * wn + 4 * nj + (lane & 3);
            float b0 = bc[2 * nj], b1 = bc[2 * nj + 1];
            dst[(size_t)row * 64 + colp] =
                pack_f16x2((acc[mi][nj][0] + b0) * osc, (acc[mi][nj][1] + b1) * osc);
            dst[(size_t)(row + 8) * 64 + colp] =
                pack_f16x2((acc[mi][nj][2] + b0) * osc, (acc[mi][nj][3] + b1) * osc);
        }
}

// ===================== Kernel B: producer/consumer mbarrier flash attention =====================
// grid (32,4) x 288 thr (9 warps). Warp 8 = producer; warps 0-7 = consumers (4qg x 2kh).
// smem: F@0 (32K persistent), stages s=0..2 @32K+s*64K (G 32K + V 32K each),
//       misc @229376: bvs 512B, lred 1KB @+512, mbars @+1536 (full[3], empty[3]).
#define SM_F    0
#define SM_STG  32768
#define SM_MISC 229376
#define SM_ATTN (229376 + 2048 + 1024)   // = 232448 (max dynamic smem)

__global__ __launch_bounds__(288, 1)
void attn_kernel(const float* __restrict__ x,
                 const float* __restrict__ Wv,
                 const float* __restrict__ bv,
                 const float* __restrict__ gamma_p,
                 float* __restrict__ out)
{
    extern __shared__ char smraw[];
    const uint32_t sbase = smem_u32(smraw);
    const uint32_t sal   = (sbase + 1023u) & ~1023u;
    char* smp = smraw + (sal - sbase);

    const int tid  = threadIdx.x;
    const int lane = tid & 31;
    const int wid  = tid >> 5;
    const int qg   = wid & 3;          // consumer: 32-q-row group
    const int kh   = wid >> 2;         // consumer: 64-key half (2 = producer warp)
    const int qw   = 32 * qg;
    const int b    = blockIdx.y;
    const int q0   = blockIdx.x * QT;

    float* bvs  = (float*)(smp + SM_MISC);
    float* lred = (float*)(smp + SM_MISC + 512);
    const uint32_t MB_FULL  = sal + SM_MISC + 1536;
    const uint32_t MB_EMPTY = sal + SM_MISC + 1536 + 24;
    if (tid < 128) bvs[tid] = bv[tid];
    if (tid == 0) {
        #pragma unroll
        for (int s = 0; s < 3; ++s) {
            MBAR_INIT(MB_FULL + 8 * s, 1);
            MBAR_INIT(MB_EMPTY + 8 * s, 8);
        }
    }

    // stage F tile (pre-scaled by log2e) — persistent
    for (int idx = tid; idx < 2048; idx += 288) {
        int r = idx >> 4, kc = idx & 15;
        uint4 v = *(const uint4*)(Fb + (size_t)(b * NN + q0 + r) * CC + kc * 8);
        *(uint4*)(smp + SM_F + blk_off(r, kc * 8)) = v;
    }
    __syncthreads();   // mbarriers + F visible

    const __half* Gbase = Gb + (size_t)b * NN * CC;
    const __half* Vbase = Vb + (size_t)b * NN * CC;

    uint32_t ctx[2][16][2];
    #pragma unroll
    for (int h = 0; h < 2; ++h)
        #pragma unroll
        for (int t = 0; t < 16; ++t) { ctx[h][t][0] = 0u; ctx[h][t][1] = 0u; }
    uint32_t lacc[2][2] = {{0u, 0u}, {0u, 0u}};

    if (wid == 8) {
        // ================= producer =================
        for (int it = 0; it < ITERS; ++it) {
            const int s = it % 3, n = it / 3;
            if (n > 0) MBAR_WAIT(MB_EMPTY + 8 * s, (n - 1) & 1);
            const uint32_t ST = sal + SM_STG + (uint32_t)s * 65536;
            const __half* gsrc = Gbase + (size_t)it * MT * CC;
            const __half* vsrc = Vbase + (size_t)it * MT * CC;
            for (int idx = lane; idx < 2048; idx += 32) {
                int r = idx >> 4, kc = idx & 15;
                uint32_t off = blk_off(r, kc * 8);
                cp16(ST + off,         gsrc + (size_t)r * CC + kc * 8);
                cp16(ST + 32768 + off, vsrc + (size_t)r * CC + kc * 8);
            }
            CP_COMMIT();
            CP_WAITALL();
            if (lane == 0) MBAR_ARRIVE(MB_FULL + 8 * s);
        }
    } else {
        // ================= consumers =================
        for (int it = 0; it < ITERS; ++it) {
            const int s = it % 3, n = it / 3;
            MBAR_WAIT(MB_FULL + 8 * s, n & 1);
            const uint32_t GT = sal + SM_STG + (uint32_t)s * 65536;
            const uint32_t VT = GT + 32768;

            // ---- S = F @ G^T (warp's 64-key half), f16 accum ----
            uint32_t pg[2][8][2];
            #pragma unroll
            for (int h = 0; h < 2; ++h)
                #pragma unroll
                for (int j = 0; j < 8; ++j) { pg[h][j][0] = 0u; pg[h][j][1] = 0u; }

            #pragma unroll
            for (int ks = 0; ks < 8; ++ks) {
                const int kcol = 16 * ks + 8 * (lane >> 4);
                uint32_t a0[4], a1[4];
                ldsm_x4(a0, sal + SM_F + blk_off(qw + (lane & 15), kcol));
                ldsm_x4(a1, sal + SM_F + blk_off(qw + 16 + (lane & 15), kcol));
                #pragma unroll
                for (int g = 0; g < 4; ++g) {
                    uint32_t bt[4];
                    ldsm_x4(bt, GT + blk_off(64 * kh + 16 * g + (lane & 15), kcol));
                    mma_f16acc2(pg[0][2 * g][0],     pg[0][2 * g][1],
                                a0[0], a0[1], a0[2], a0[3], bt[0], bt[2]);
                    mma_f16acc2(pg[0][2 * g + 1][0], pg[0][2 * g + 1][1],
                                a0[0], a0[1], a0[2], a0[3], bt[1], bt[3]);
                    mma_f16acc2(pg[1][2 * g][0],     pg[1][2 * g][1],
                                a1[0], a1[1], a1[2], a1[3], bt[0], bt[2]);
                    mma_f16acc2(pg[1][2 * g + 1][0], pg[1][2 * g + 1][1],
                                a1[0], a1[1], a1[2], a1[3], bt[1], bt[3]);
                }
            }

            // ---- P = 2^S; row sums (ALU) ----
            #pragma unroll
            for (int h = 0; h < 2; ++h)
                #pragma unroll
                for (int j = 0; j < 8; ++j) {
                    pg[h][j][0] = ex2_f16x2(pg[h][j][0]);
                    pg[h][j][1] = ex2_f16x2(pg[h][j][1]);
                    lacc[h][0] = hadd2u(lacc[h][0], pg[h][j][0]);
                    lacc[h][1] = hadd2u(lacc[h][1], pg[h][j][1]);
                }

            // ---- ctx += P @ V ----
            #pragma unroll
            for (int kt = 0; kt < 4; ++kt) {
                const int vrow = 64 * kh + 16 * kt + (lane & 15);
                const int ncol = 8 * (lane >> 4);
                #pragma unroll
                for (int cg = 0; cg < 8; ++cg) {
                    uint32_t bt[4];
                    ldsm_x4_t(bt, VT + blk_off(vrow, 16 * cg + ncol));
                    #pragma unroll
                    for (int h = 0; h < 2; ++h) {
                        mma_f16acc2(ctx[h][2 * cg][0],     ctx[h][2 * cg][1],
                                    pg[h][2 * kt][0], pg[h][2 * kt][1],
                                    pg[h][2 * kt + 1][0], pg[h][2 * kt + 1][1], bt[0], bt[1]);
                        mma_f16acc2(ctx[h][2 * cg + 1][0], ctx[h][2 * cg + 1][1],
                                    pg[h][2 * kt][0], pg[h][2 * kt][1],
                                    pg[h][2 * kt + 1][0], pg[h][2 * kt + 1][1], bt[2], bt[3]);
                    }
                }
            }
            if (lane == 0) MBAR_ARRIVE(MB_EMPTY + 8 * s);
        }
    }
    __syncthreads();   // all consumers + producer done; stages reusable

    // ---- l partials (consumers only) ----
    if (wid < 8) {
        #pragma unroll
        for (int h = 0; h < 2; ++h) {
            float2 v0 = __half22float2(*(__half2*)&lacc[h][0]);
            float2 v1 = __half22float2(*(__half2*)&lacc[h][1]);
            float l0 = v0.x + v0.y;
            float l1 = v1.x + v1.y;
            l0 += __shfl_xor_sync(0xffffffffu, l0, 1);
            l0 += __shfl_xor_sync(0xffffffffu, l0, 2);
            l1 += __shfl_xor_sync(0xffffffffu, l1, 1);
            l1 += __shfl_xor_sync(0xffffffffu, l1, 2);
            if ((lane & 3) == 0) {
                int row = qw + 16 * h + (lane >> 2);
                lred[row * 2 + kh]       = l0;
                lred[(row + 8) * 2 + kh] = l1;
            }
        }
    }

    // ---- phase 1: kh==0 stores ctx tile into F region ----
    if (kh == 0) {
        #pragma unroll
        for (int h = 0; h < 2; ++h)
            #pragma unroll
            for (int t = 0; t < 16; ++t) {
                int row = qw + 16 * h + (lane >> 2);
                int col = 8 * t + 2 * (lane & 3);
                *(uint32_t*)(smp + SM_F + blk_off(row, col))     = ctx[h][t][0];
                *(uint32_t*)(smp + SM_F + blk_off(row + 8, col)) = ctx[h][t][1];
            }
    }
    __syncthreads();

    // ---- phase 2: kh==1 adds its ctx; kh==0 loads Wv tile into stage0 ----
    if (kh == 1) {
        #pragma unroll
        for (int h = 0; h < 2; ++h)
            #pragma unroll
            for (int t = 0; t < 16; ++t) {
                int row = qw + 16 * h + (lane >> 2);
                int col = 8 * t + 2 * (lane & 3);
                uint32_t* p0 = (uint32_t*)(smp + SM_F + blk_off(row, col));
                uint32_t* p1 = (uint32_t*)(smp + SM_F + blk_off(row + 8, col));
                __half2 s0 = __hadd2(*(__half2*)p0, *(__half2*)&ctx[h][t][0]);
                __half2 s1 = __hadd2(*(__half2*)p1, *(__half2*)&ctx[h][t][1]);
                *p0 = *(uint32_t*)&s0;
                *p1 = *(uint32_t*)&s1;
            }
    } else if (kh == 0) {
        #pragma unroll
        for (int idx = tid; idx < 2048; idx += 128) {   // kh==0: tid 0..127
            int r = idx >> 4, kc = idx & 15;
            const float4* s = (const float4*)(Wv + (size_t)r * CC + kc * 8);
            float4 v0 = s[0], v1 = s[1];
            uint4 pk;
            pk.x = pack_f16x2(v0.x, v0.y); pk.y = pack_f16x2(v0.z, v0.w);
            pk.z = pack_f16x2(v1.x, v1.y); pk.w = pack_f16x2(v1.z, v1.w);
            *(uint4*)(smp + SM_STG + blk_off(r, kc * 8)) = pk;
        }
    }
    __syncthreads();

    // ---- phase 3: consumers: out = (gamma/l) * (ctx @ Wv) + bv + x ----
    if (wid < 8) {
        const int qw16 = 16 * wid;
        float oac[16][4];
        #pragma unroll
        for (int t = 0; t < 16; ++t)
            #pragma unroll
            for (int e = 0; e < 4; ++e) oac[t][e] = 0.f;

        #pragma unroll
        for (int ks = 0; ks < 8; ++ks) {
            uint32_t a[4];
            ldsm_x4(a, sal + SM_F + blk_off(qw16 + (lane & 15), 16 * ks + 8 * (lane >> 4)));
            int ncol = 8 * (lane >> 4);
            #pragma unroll
            for (int g = 0; g < 8; ++g) {
                uint32_t bt[4];
                ldsm_x4_t(bt, sal + SM_STG + blk_off(16 * ks + (lane & 15), 16 * g + ncol));
                mma_f32acc(oac[2 * g],     a[0], a[1], a[2], a[3], bt[0], bt[1]);
                mma_f32acc(oac[2 * g + 1], a[0], a[1], a[2], a[3], bt[2], bt[3]);
            }
        }

        const float gamma = __ldg(gamma_p);
        const int r  = lane >> 2;
        const int c2 = 2 * (lane & 3);
        const float sc0 = gamma / (lred[(qw16 + r) * 2]     + lred[(qw16 + r) * 2 + 1]);
        const float sc1 = gamma / (lred[(qw16 + r + 8) * 2] + lred[(qw16 + r + 8) * 2 + 1]);
        #pragma unroll
        for (int t = 0; t < 16; ++t) {
            int j = 8 * t + c2;
            float bj0 = bvs[j], bj1 = bvs[j + 1];
            size_t base0 = (size_t)(b * NN + q0 + qw16 + r) * CC + j;
            size_t base1 = base0 + 8 * CC;
            float2 x0 = *(const float2*)(x + base0);
            float2 x1 = *(const float2*)(x + base1);
            float2 o0, o1;
            o0.x = oac[t][0] * sc0 + bj0 + x0.x;
            o0.y = oac[t][1] * sc0 + bj1 + x0.y;
            o1.x = oac[t][2] * sc1 + bj0 + x1.x;
            o1.y = oac[t][3] * sc1 + bj1 + x1.y;
            *(float2*)(out + base0) = o0;
            *(float2*)(out + base1) = o1;
        }
    }
}

// ===================== launch =====================
extern "C" void kernel_launch(void* const* d_in, const int* in_sizes, int n_in,
                              void* d_out, int out_size)
{
    const float* x     = (const float*)d_in[0];
    const float* Wf    = (const float*)d_in[1];
    const float* bf    = (const float*)d_in[2];
    const float* Wg    = (const float*)d_in[3];
    const float* bg    = (const float*)d_in[4];
    const float* Wh    = (const float*)d_in[5];
    const float* bh    = (const float*)d_in[6];
    const float* Wv    = (const float*)d_in[7];
    const float* bv    = (const float*)d_in[8];
    const float* gamma = (const float*)d_in[9];
    float* out = (float*)d_out;

    const int smem_proj = 2 * 32768 + 1024;
    const int smem_attn = SM_ATTN;   // 232448 = max dynamic smem

    cudaFuncSetAttribute(proj_kernel, cudaFuncAttributeMaxDynamicSharedMemorySize, smem_proj);
    cudaFuncSetAttribute(attn_kernel, cudaFuncAttributeMaxDynamicSharedMemorySize, smem_attn);

    dim3 pgrid(BATCH * NN / 128, 3);
    proj_kernel<<<pgrid, 256, smem_proj>>>(x, Wf, bf, Wg, bg, Wh, bh);

    dim3 grid(NN / QT, BATCH);
    attn_kernel<<<grid, 288, smem_attn>>>(x, Wv, bv, gamma, out);
}

// round 17
// speedup vs baseline: 1.2844x; 1.2844x over previous
#include <cuda_runtime.h>
#include <cuda_fp16.h>
#include <math.h>
#include <stdint.h>

#define BATCH 4
#define NN 4096
#define CC 128
#define QT 128
#define MT 128
#define ITERS (NN / MT)

// f16 scratch, row-major [b*n][c]. Fb is pre-scaled by log2(e).
__device__ __align__(16) __half Fb[BATCH * NN * CC];
__device__ __align__(16) __half Gb[BATCH * NN * CC];
__device__ __align__(16) __half Vb[BATCH * NN * CC];

// ===================== helpers =====================
__device__ __forceinline__ uint32_t smem_u32(const void* p) {
    uint32_t a;
    asm("{ .reg .u64 t; cvta.to.shared.u64 t, %1; cvt.u32.u64 %0, t; }" : "=r"(a) : "l"(p));
    return a;
}
__device__ __forceinline__ uint32_t pack_f16x2(float lo, float hi) {
    uint32_t r;
    asm("cvt.rn.f16x2.f32 %0, %1, %2;" : "=r"(r) : "f"(hi), "f"(lo));
    return r;
}
__device__ __forceinline__ uint32_t ex2_f16x2(uint32_t a) {
    uint32_t r;
    asm("ex2.approx.f16x2 %0, %1;" : "=r"(r) : "r"(a));
    return r;
}
__device__ __forceinline__ uint32_t hadd2u(uint32_t a, uint32_t b) {
    uint32_t r;
    asm("add.f16x2 %0, %1, %2;" : "=r"(r) : "r"(a), "r"(b));
    return r;
}
// blocked SW128 layout for a [128 rows][128 halves] f16 tile (32 KB)
__device__ __forceinline__ uint32_t blk_off(int r, int k) {
    uint32_t byte = ((uint32_t)((r >> 3) + ((k >> 6) << 4)) << 10)
                  + ((uint32_t)(r & 7) << 7) + ((uint32_t)(k & 63) << 1);
    return byte ^ ((byte >> 3) & 0x70);
}
__device__ __forceinline__ void ldsm_x4(uint32_t (&r)[4], uint32_t addr) {
    asm volatile("ldmatrix.sync.aligned.m8n8.x4.shared.b16 {%0,%1,%2,%3}, [%4];"
                 : "=r"(r[0]), "=r"(r[1]), "=r"(r[2]), "=r"(r[3]) : "r"(addr));
}
__device__ __forceinline__ void ldsm_x4_t(uint32_t (&r)[4], uint32_t addr) {
    asm volatile("ldmatrix.sync.aligned.m8n8.x4.trans.shared.b16 {%0,%1,%2,%3}, [%4];"
                 : "=r"(r[0]), "=r"(r[1]), "=r"(r[2]), "=r"(r[3]) : "r"(addr));
}
__device__ __forceinline__ void mma_f32acc(float (&d)[4], uint32_t a0, uint32_t a1,
                                           uint32_t a2, uint32_t a3,
                                           uint32_t b0, uint32_t b1) {
    asm volatile("mma.sync.aligned.m16n8k16.row.col.f32.f16.f16.f32 "
                 "{%0,%1,%2,%3},{%4,%5,%6,%7},{%8,%9},{%0,%1,%2,%3};"
                 : "+f"(d[0]), "+f"(d[1]), "+f"(d[2]), "+f"(d[3])
                 : "r"(a0), "r"(a1), "r"(a2), "r"(a3), "r"(b0), "r"(b1));
}
__device__ __forceinline__ void mma_f16acc2(uint32_t& d0, uint32_t& d1,
                                            uint32_t a0, uint32_t a1,
                                            uint32_t a2, uint32_t a3,
                                            uint32_t b0, uint32_t b1) {
    asm volatile("mma.sync.aligned.m16n8k16.row.col.f16.f16.f16.f16 "
                 "{%0,%1},{%2,%3,%4,%5},{%6,%7},{%0,%1};"
                 : "+r"(d0), "+r"(d1)
                 : "r"(a0), "r"(a1), "r"(a2), "r"(a3), "r"(b0), "r"(b1));
}
__device__ __forceinline__ void cp16(uint32_t d, const void* s) {
    asm volatile("cp.async.cg.shared.global [%0], [%1], 16;" :: "r"(d), "l"(s) : "memory");
}
#define CP_COMMIT() asm volatile("cp.async.commit_group;" ::: "memory")
#define CP_WAIT0()  asm volatile("cp.async.wait_group 0;" ::: "memory")
#define CP_WAIT1()  asm volatile("cp.async.wait_group 1;" ::: "memory")

#define LOG2E 1.4426950408889634f

// ===================== Kernel A: projections, 2 row-tiles per CTA =====================
// grid (64 tile-pairs, 3 weights) x 256 thr. W loaded once, reused for 2 sub-tiles.
__global__ __launch_bounds__(256, 1)
void proj_kernel(const float* __restrict__ x,
                 const float* __restrict__ Wf, const float* __restrict__ bf,
                 const float* __restrict__ Wg, const float* __restrict__ bg,
                 const float* __restrict__ Wh, const float* __restrict__ bh)
{
    extern __shared__ char smraw[];
    const uint32_t sbase = smem_u32(smraw);
    const uint32_t sal   = (sbase + 1023u) & ~1023u;
    char* smp = smraw + (sal - sbase);
    const uint32_t XT = sal, WT = sal + 32768;

    const int tid  = threadIdx.x;
    const int lane = tid & 31;
    const int wid  = tid >> 5;
    const int wm   = wid & 3;
    const int wn   = wid >> 2;
    const int w    = blockIdx.y;

    const float* W  = (w == 0) ? Wf : (w == 1 ? Wg : Wh);
    const float* bs = (w == 0) ? bf : (w == 1 ? bg : bh);
    const float osc = (w == 0) ? LOG2E : 1.0f;
    uint32_t* dst = (uint32_t*)(w == 0 ? Fb : (w == 1 ? Gb : Vb));

    // load weight tile once
    #pragma unroll
    for (int idx = tid; idx < 2048; idx += 256) {
        int r = idx >> 4, kc = idx & 15;
        const float4* s1 = (const float4*)(W + (size_t)r * CC + kc * 8);
        float4 v0 = s1[0], v1 = s1[1];
        uint4 pk;
        pk.x = pack_f16x2(v0.x, v0.y); pk.y = pack_f16x2(v0.z, v0.w);
        pk.z = pack_f16x2(v1.x, v1.y); pk.w = pack_f16x2(v1.z, v1.w);
        *(uint4*)(smp + (WT - sal) + blk_off(r, kc * 8)) = pk;
    }
    float bc[16];
    #pragma unroll
    for (int t = 0; t < 16; ++t)
        bc[t] = bs[64 * wn + 8 * (t >> 1) + 2 * (lane & 3) + (t & 1)];

    #pragma unroll
    for (int sub = 0; sub < 2; ++sub) {
        const int row0 = blockIdx.x * 256 + sub * 128;
        __syncthreads();   // prev sub-tile GEMM done before XT overwrite; WT ready
        #pragma unroll
        for (int idx = tid; idx < 2048; idx += 256) {
            int r = idx >> 4, kc = idx & 15;
            const float4* s0 = (const float4*)(x + (size_t)(row0 + r) * CC + kc * 8);
            float4 v0 = s0[0], v1 = s0[1];
            uint4 pk;
            pk.x = pack_f16x2(v0.x, v0.y); pk.y = pack_f16x2(v0.z, v0.w);
            pk.z = pack_f16x2(v1.x, v1.y); pk.w = pack_f16x2(v1.z, v1.w);
            *(uint4*)(smp + (XT - sal) + blk_off(r, kc * 8)) = pk;
        }
        __syncthreads();

        float acc[2][8][4];
        #pragma unroll
        for (int i = 0; i < 2; ++i)
            #pragma unroll
            for (int j = 0; j < 8; ++j)
                #pragma unroll
                for (int e = 0; e < 4; ++e) acc[i][j][e] = 0.f;

        #pragma unroll
        for (int ks = 0; ks < 8; ++ks) {
            uint32_t a0[4], a1[4];
            int kcol = 16 * ks + 8 * (lane >> 4);
            ldsm_x4(a0, XT + blk_off(32 * wm + (lane & 15), kcol));
            ldsm_x4(a1, XT + blk_off(32 * wm + 16 + (lane & 15), kcol));
            #pragma unroll
            for (int g = 0; g < 4; ++g) {
                uint32_t bt[4];
                ldsm_x4_t(bt, WT + blk_off(16 * ks + (lane & 15),
                                           64 * wn + 16 * g + 8 * (lane >> 4)));
                mma_f32acc(acc[0][2 * g],     a0[0], a0[1], a0[2], a0[3], bt[0], bt[1]);
                mma_f32acc(acc[0][2 * g + 1], a0[0], a0[1], a0[2], a0[3], bt[2], bt[3]);
                mma_f32acc(acc[1][2 * g],     a1[0], a1[1], a1[2], a1[3], bt[0], bt[1]);
                mma_f32acc(acc[1][2 * g + 1], a1[0], a1[1], a1[2], a1[3], bt[2], bt[3]);
            }
        }

        #pragma unroll
        for (int mi = 0; mi < 2; ++mi)
            #pragma unroll
            for (int nj = 0; nj < 8; ++nj) {
                int row  = row0 + 32 * wm + 16 * mi + (lane >> 2);
                int colp = 32 * wn + 4 * nj + (lane & 3);
                float b0 = bc[2 * nj], b1 = bc[2 * nj + 1];
                dst[(size_t)row * 64 + colp] =
                    pack_f16x2((acc[mi][nj][0] + b0) * osc, (acc[mi][nj][1] + b1) * osc);
                dst[(size_t)(row + 8) * 64 + colp] =
                    pack_f16x2((acc[mi][nj][2] + b0) * osc, (acc[mi][nj][3] + b1) * osc);
            }
    }
}

// ===================== Kernel B: low-register flash attention (R15, best) =====================
// grid (32,4) x 256 thr. 8 warps = 4 qg x 2 kh; warp owns q[32qg,+32) x keys[64kh,+64).
// F stays resident in smem; A-fragments re-read per iteration.
// smem: F@0 (32K, persistent), B0@32K (G+V 64K), B1@98304 (64K),
//       bvs@163840 (512B), lred@+512 (1KB). Epilogue: ctx->F, Wv->B0.
#define SM_F    0
#define SM_GV   32768
#define SM_MISC 163840
#define SM_ATTN (163840 + 1536 + 1024)

__global__ __launch_bounds__(256, 1)
void attn_kernel(const float* __restrict__ x,
                 const float* __restrict__ Wv,
                 const float* __restrict__ bv,
                 const float* __restrict__ gamma_p,
                 float* __restrict__ out)
{
    extern __shared__ char smraw[];
    const uint32_t sbase = smem_u32(smraw);
    const uint32_t sal   = (sbase + 1023u) & ~1023u;
    char* smp = smraw + (sal - sbase);

    const int tid  = threadIdx.x;
    const int lane = tid & 31;
    const int wid  = tid >> 5;
    const int qg   = wid & 3;          // 32-q-row group
    const int kh   = wid >> 2;         // 64-key half
    const int qw   = 32 * qg;
    const int b    = blockIdx.y;
    const int q0   = blockIdx.x * QT;

    float* bvs  = (float*)(smp + SM_MISC);
    float* lred = (float*)(smp + SM_MISC + 512);
    if (tid < 128) bvs[tid] = bv[tid];

    const __half* Gbase = Gb + (size_t)b * NN * CC;
    const __half* Vbase = Vb + (size_t)b * NN * CC;

    // stage F tile (pre-scaled by log2e) — persistent through the loop
    #pragma unroll
    for (int idx = tid; idx < 2048; idx += 256) {
        int r = idx >> 4, kc = idx & 15;
        uint4 v = *(const uint4*)(Fb + (size_t)(b * NN + q0 + r) * CC + kc * 8);
        *(uint4*)(smp + SM_F + blk_off(r, kc * 8)) = v;
    }

    // prefetch tile 0 into buffer 0
    #pragma unroll
    for (int idx = tid; idx < 2048; idx += 256) {
        int r = idx >> 4, kc = idx & 15;
        uint32_t off = blk_off(r, kc * 8);
        cp16(sal + SM_GV + off,         Gbase + (size_t)r * CC + kc * 8);
        cp16(sal + SM_GV + 32768 + off, Vbase + (size_t)r * CC + kc * 8);
    }
    CP_COMMIT();

    uint32_t ctx[2][16][2];            // f16 accum: 32q x 128c
    #pragma unroll
    for (int h = 0; h < 2; ++h)
        #pragma unroll
        for (int t = 0; t < 16; ++t) { ctx[h][t][0] = 0u; ctx[h][t][1] = 0u; }
    uint32_t lacc[2][2] = {{0u, 0u}, {0u, 0u}};

    int buf = 0;
    for (int it = 0; it < ITERS; ++it) {
        __syncthreads();               // all warps done with buf^1 (incl. F at it=0)
        if (it + 1 < ITERS) {
            int nb = buf ^ 1;
            const __half* gsrc = Gbase + (size_t)(it + 1) * MT * CC;
            const __half* vsrc = Vbase + (size_t)(it + 1) * MT * CC;
            #pragma unroll
            for (int idx = tid; idx < 2048; idx += 256) {
                int r = idx >> 4, kc = idx & 15;
                uint32_t off = blk_off(r, kc * 8);
                cp16(sal + SM_GV + nb * 65536 + off,         gsrc + (size_t)r * CC + kc * 8);
                cp16(sal + SM_GV + nb * 65536 + 32768 + off, vsrc + (size_t)r * CC + kc * 8);
            }
            CP_COMMIT();
            CP_WAIT1();
        } else {
            CP_WAIT0();
        }
        __syncthreads();               // tile `buf` visible

        const uint32_t GT = sal + SM_GV + buf * 65536;
        const uint32_t VT = GT + 32768;

        // ---- S = F @ G^T (warp's 64-key half), f16 accum; aF re-read per ks ----
        uint32_t pg[2][8][2];
        #pragma unroll
        for (int h = 0; h < 2; ++h)
            #pragma unroll
            for (int j = 0; j < 8; ++j) { pg[h][j][0] = 0u; pg[h][j][1] = 0u; }

        #pragma unroll
        for (int ks = 0; ks < 8; ++ks) {
            const int kcol = 16 * ks + 8 * (lane >> 4);
            uint32_t a0[4], a1[4];
            ldsm_x4(a0, sal + SM_F + blk_off(qw + (lane & 15), kcol));
            ldsm_x4(a1, sal + SM_F + blk_off(qw + 16 + (lane & 15), kcol));
            #pragma unroll
            for (int g = 0; g < 4; ++g) {
                uint32_t bt[4];
                ldsm_x4(bt, GT + blk_off(64 * kh + 16 * g + (lane & 15), kcol));
                mma_f16acc2(pg[0][2 * g][0],     pg[0][2 * g][1],
                            a0[0], a0[1], a0[2], a0[3], bt[0], bt[2]);
                mma_f16acc2(pg[0][2 * g + 1][0], pg[0][2 * g + 1][1],
                            a0[0], a0[1], a0[2], a0[3], bt[1], bt[3]);
                mma_f16acc2(pg[1][2 * g][0],     pg[1][2 * g][1],
                            a1[0], a1[1], a1[2], a1[3], bt[0], bt[2]);
                mma_f16acc2(pg[1][2 * g + 1][0], pg[1][2 * g + 1][1],
                            a1[0], a1[1], a1[2], a1[3], bt[1], bt[3]);
            }
        }

        // ---- P = 2^S in place; row sums on ALU pipe ----
        #pragma unroll
        for (int h = 0; h < 2; ++h)
            #pragma unroll
            for (int j = 0; j < 8; ++j) {
                pg[h][j][0] = ex2_f16x2(pg[h][j][0]);
                pg[h][j][1] = ex2_f16x2(pg[h][j][1]);
                lacc[h][0] = hadd2u(lacc[h][0], pg[h][j][0]);
                lacc[h][1] = hadd2u(lacc[h][1], pg[h][j][1]);
            }

        // ---- ctx += P @ V (warp's 64 key rows) ----
        #pragma unroll
        for (int kt = 0; kt < 4; ++kt) {
            const int vrow = 64 * kh + 16 * kt + (lane & 15);
            const int ncol = 8 * (lane >> 4);
            #pragma unroll
            for (int cg = 0; cg < 8; ++cg) {
                uint32_t bt[4];
                ldsm_x4_t(bt, VT + blk_off(vrow, 16 * cg + ncol));
                #pragma unroll
                for (int h = 0; h < 2; ++h) {
                    mma_f16acc2(ctx[h][2 * cg][0],     ctx[h][2 * cg][1],
                                pg[h][2 * kt][0], pg[h][2 * kt][1],
                                pg[h][2 * kt + 1][0], pg[h][2 * kt + 1][1], bt[0], bt[1]);
                    mma_f16acc2(ctx[h][2 * cg + 1][0], ctx[h][2 * cg + 1][1],
                                pg[h][2 * kt][0], pg[h][2 * kt][1],
                                pg[h][2 * kt + 1][0], pg[h][2 * kt + 1][1], bt[2], bt[3]);
                }
            }
        }
        buf ^= 1;
    }
    __syncthreads();   // all warps done with F + GV buffers

    // ---- l partials ----
    #pragma unroll
    for (int h = 0; h < 2; ++h) {
        float2 v0 = __half22float2(*(__half2*)&lacc[h][0]);
        float2 v1 = __half22float2(*(__half2*)&lacc[h][1]);
        float l0 = v0.x + v0.y;
        float l1 = v1.x + v1.y;
        l0 += __shfl_xor_sync(0xffffffffu, l0, 1);
        l0 += __shfl_xor_sync(0xffffffffu, l0, 2);
        l1 += __shfl_xor_sync(0xffffffffu, l1, 1);
        l1 += __shfl_xor_sync(0xffffffffu, l1, 2);
        if ((lane & 3) == 0) {
            int row = qw + 16 * h + (lane >> 2);
            lred[row * 2 + kh]       = l0;
            lred[(row + 8) * 2 + kh] = l1;
        }
    }

    // ---- phase 1: kh=0 stores ctx tile into F region ----
    if (kh == 0) {
        #pragma unroll
        for (int h = 0; h < 2; ++h)
            #pragma unroll
            for (int t = 0; t < 16; ++t) {
                int row = qw + 16 * h + (lane >> 2);
                int col = 8 * t + 2 * (lane & 3);
                *(uint32_t*)(smp + SM_F + blk_off(row, col))     = ctx[h][t][0];
                *(uint32_t*)(smp + SM_F + blk_off(row + 8, col)) = ctx[h][t][1];
            }
    }
    __syncthreads();

    // ---- phase 2: kh=1 adds its ctx; kh=0 warps load Wv tile into B0 ----
    if (kh == 1) {
        #pragma unroll
        for (int h = 0; h < 2; ++h)
            #pragma unroll
            for (int t = 0; t < 16; ++t) {
                int row = qw + 16 * h + (lane >> 2);
                int col = 8 * t + 2 * (lane & 3);
                uint32_t* p0 = (uint32_t*)(smp + SM_F + blk_off(row, col));
                uint32_t* p1 = (uint32_t*)(smp + SM_F + blk_off(row + 8, col));
                __half2 s0 = __hadd2(*(__half2*)p0, *(__half2*)&ctx[h][t][0]);
                __half2 s1 = __hadd2(*(__half2*)p1, *(__half2*)&ctx[h][t][1]);
                *p0 = *(uint32_t*)&s0;
                *p1 = *(uint32_t*)&s1;
            }
    } else {
        #pragma unroll
        for (int idx = tid; idx < 2048; idx += 128) {   // kh==0: 128 threads
            int r = idx >> 4, kc = idx & 15;
            const float4* s = (const float4*)(Wv + (size_t)r * CC + kc * 8);
            float4 v0 = s[0], v1 = s[1];
            uint4 pk;
            pk.x = pack_f16x2(v0.x, v0.y); pk.y = pack_f16x2(v0.z, v0.w);
            pk.z = pack_f16x2(v1.x, v1.y); pk.w = pack_f16x2(v1.z, v1.w);
            *(uint4*)(smp + SM_GV + blk_off(r, kc * 8)) = pk;
        }
    }
    __syncthreads();

    // ---- phase 3: all 8 warps: out_rows = warp's 16q slice ----
    const int qw16 = 16 * wid;
    float oac[16][4];
    #pragma unroll
    for (int t = 0; t < 16; ++t)
        #pragma unroll
        for (int e = 0; e < 4; ++e) oac[t][e] = 0.f;

    #pragma unroll
    for (int ks = 0; ks < 8; ++ks) {
        uint32_t a[4];
        ldsm_x4(a, sal + SM_F + blk_off(qw16 + (lane & 15), 16 * ks + 8 * (lane >> 4)));
        int ncol = 8 * (lane >> 4);
        #pragma unroll
        for (int g = 0; g < 8; ++g) {
            uint32_t bt[4];
            ldsm_x4_t(bt, sal + SM_GV + blk_off(16 * ks + (lane & 15), 16 * g + ncol));
            mma_f32acc(oac[2 * g],     a[0], a[1], a[2], a[3], bt[0], bt[1]);
            mma_f32acc(oac[2 * g + 1], a[0], a[1], a[2], a[3], bt[2], bt[3]);
        }
    }

    const float gamma = __ldg(gamma_p);
    const int r  = lane >> 2;
    const int c2 = 2 * (lane & 3);
    const float sc0 = gamma / (lred[(qw16 + r) * 2]     + lred[(qw16 + r) * 2 + 1]);
    const float sc1 = gamma / (lred[(qw16 + r + 8) * 2] + lred[(qw16 + r + 8) * 2 + 1]);
    #pragma unroll
    for (int t = 0; t < 16; ++t) {
        int j = 8 * t + c2;
        float bj0 = bvs[j], bj1 = bvs[j + 1];
        size_t base0 = (size_t)(b * NN + q0 + qw16 + r) * CC + j;
        size_t base1 = base0 + 8 * CC;
        float2 x0 = *(const float2*)(x + base0);
        float2 x1 = *(const float2*)(x + base1);
        float2 o0, o1;
        o0.x = oac[t][0] * sc0 + bj0 + x0.x;
        o0.y = oac[t][1] * sc0 + bj1 + x0.y;
        o1.x = oac[t][2] * sc1 + bj0 + x1.x;
        o1.y = oac[t][3] * sc1 + bj1 + x1.y;
        *(float2*)(out + base0) = o0;
        *(float2*)(out + base1) = o1;
    }
}

// ===================== launch =====================
extern "C" void kernel_launch(void* const* d_in, const int* in_sizes, int n_in,
                              void* d_out, int out_size)
{
    const float* x     = (const float*)d_in[0];
    const float* Wf    = (const float*)d_in[1];
    const float* bf    = (const float*)d_in[2];
    const float* Wg    = (const float*)d_in[3];
    const float* bg    = (const float*)d_in[4];
    const float* Wh    = (const float*)d_in[5];
    const float* bh    = (const float*)d_in[6];
    const float* Wv    = (const float*)d_in[7];
    const float* bv    = (const float*)d_in[8];
    const float* gamma = (const float*)d_in[9];
    float* out = (float*)d_out;

    const int smem_proj = 2 * 32768 + 1024;
    const int smem_attn = SM_ATTN;

    cudaFuncSetAttribute(proj_kernel, cudaFuncAttributeMaxDynamicSharedMemorySize, smem_proj);
    cudaFuncSetAttribute(attn_kernel, cudaFuncAttributeMaxDynamicSharedMemorySize, smem_attn);

    dim3 pgrid(BATCH * NN / 256, 3);
    proj_kernel<<<pgrid, 256, smem_proj>>>(x, Wf, bf, Wg, bg, Wh, bh);

    dim3 grid(NN / QT, BATCH);
    attn_kernel<<<grid, 256, smem_attn>>>(x, Wv, bv, gamma, out);
}